// round 10
// baseline (speedup 1.0000x reference)
#include <cuda_runtime.h>
#include <cstdint>

#define BB 512   // batch
#define TT 256   // seq len
#define HH 64    // hidden
#define GG 256   // 4*H gates
#define DD 64    // input/output dim

// Scratch (static __device__ arrays — allocation-free per harness rules)
__device__ float g_xg[(size_t)TT * BB * GG];   // gate pre-acts [n][unit*4+gate]
__device__ float g_hseq[(size_t)TT * BB * HH]; // hidden sequence [T][B][H]
__device__ float g_lat[BB * HH];               // encoder latent [B][H]
__device__ float g_xgc[BB * GG];               // dec0 constant xg [B][unit*4+gate]

typedef unsigned long long u64;

__device__ __forceinline__ u64 ffma2(u64 a, u64 b, u64 c) {
    u64 d;
    asm("fma.rn.f32x2 %0, %1, %2, %3;" : "=l"(d) : "l"(a), "l"(b), "l"(c));
    return d;
}
__device__ __forceinline__ float2 up2(u64 v) {
    float lo, hi;
    asm("mov.b64 {%0, %1}, %2;" : "=f"(lo), "=f"(hi) : "l"(v));
    return make_float2(lo, hi);
}

__device__ __forceinline__ float fsigm(float x) {
    return __fdividef(1.0f, 1.0f + __expf(-x));
}
__device__ __forceinline__ float ftanh(float x) {
    return 1.0f - __fdividef(2.0f, __expf(2.0f * x) + 1.0f);
}

__device__ __forceinline__ uint32_t tf32_of(float x) {
    uint32_t u;
    asm("cvt.rna.tf32.f32 %0, %1;" : "=r"(u) : "f"(x));
    return u;
}

__device__ __forceinline__ void mma_tf32(
    float* d, const uint32_t* a, const uint32_t* b)
{
    asm volatile(
        "mma.sync.aligned.m16n8k8.row.col.f32.tf32.tf32.f32 "
        "{%0,%1,%2,%3}, {%4,%5,%6,%7}, {%8,%9}, {%0,%1,%2,%3};"
        : "+f"(d[0]), "+f"(d[1]), "+f"(d[2]), "+f"(d[3])
        : "r"(a[0]), "r"(a[1]), "r"(a[2]), "r"(a[3]),
          "r"(b[0]), "r"(b[1]));
}

// ---------------------------------------------------------------------------
// Tensor-core tf32 GEMM: sum_k X[row n][k] * W[col][k] + bias.
// X row n addressed via n = t*BB + b -> X + b*st_b + t*st_t (+k). K = 64.
// Block tile 128(m) x 64(n), 256 threads = 8 warps (4m x 2n), warp tile 32x32.
// PERM=0 (xg): blockIdx.y IS the gate (64-col tiles align with gates);
//   store interleaved: out[n*GG + unit*4 + gate], unit = cc.
// PERM=1 (FC): out[(b*TT+t)*DD + cc] float2.
// ---------------------------------------------------------------------------
template<int PERM>
__global__ __launch_bounds__(256) void gemm_tc(
    const float* __restrict__ X, int st_b, int st_t,
    const float* __restrict__ W,
    const float* __restrict__ bias1, const float* __restrict__ bias2,
    float* __restrict__ out, int ostride)
{
    extern __shared__ uint32_t smu[];
    uint32_t* Xs = smu;                    // [128][66]
    uint32_t* Ws = smu + 128 * 66;         // [64][66]
    float*    Bs = (float*)(smu + 128 * 66 + 64 * 66);  // [64]

    const int tid  = threadIdx.x;
    const int row0 = blockIdx.x * 128;
    const int col0 = blockIdx.y * 64;

    #pragma unroll
    for (int i = 0; i < 8; i++) {
        int idx = tid + i * 256;
        int m   = idx & 127;
        int k4  = idx >> 7;
        int n   = row0 + m;
        int b   = n & (BB - 1);
        int t   = n >> 9;
        float4 v = *(const float4*)(X + (size_t)b * st_b + (size_t)t * st_t + k4 * 4);
        uint32_t* p = Xs + m * 66 + k4 * 4;
        p[0] = tf32_of(v.x); p[1] = tf32_of(v.y);
        p[2] = tf32_of(v.z); p[3] = tf32_of(v.w);
    }
    #pragma unroll
    for (int i = 0; i < 4; i++) {
        int idx = tid + i * 256;
        int g   = idx & 63;
        int k4  = idx >> 6;
        float4 v = *(const float4*)(W + (size_t)(col0 + g) * 64 + k4 * 4);
        uint32_t* p = Ws + g * 66 + k4 * 4;
        p[0] = tf32_of(v.x); p[1] = tf32_of(v.y);
        p[2] = tf32_of(v.z); p[3] = tf32_of(v.w);
    }
    if (tid < 64)
        Bs[tid] = (bias1 ? bias1[col0 + tid] : 0.f)
                + (bias2 ? bias2[col0 + tid] : 0.f);
    __syncthreads();

    const int lane = tid & 31;
    const int gid  = lane >> 2;
    const int tg   = lane & 3;
    const int warp = tid >> 5;
    const int wm   = warp & 3;
    const int wn   = warp >> 2;

    float acc[2][4][4];
    #pragma unroll
    for (int mt = 0; mt < 2; mt++)
        #pragma unroll
        for (int nt = 0; nt < 4; nt++)
            #pragma unroll
            for (int r = 0; r < 4; r++) acc[mt][nt][r] = 0.f;

    #pragma unroll
    for (int s = 0; s < 8; s++) {
        const int kk = s * 8;
        uint32_t a[2][4];
        #pragma unroll
        for (int mt = 0; mt < 2; mt++) {
            int r = wm * 32 + mt * 16 + gid;
            a[mt][0] = Xs[r * 66 + kk + tg];
            a[mt][1] = Xs[(r + 8) * 66 + kk + tg];
            a[mt][2] = Xs[r * 66 + kk + tg + 4];
            a[mt][3] = Xs[(r + 8) * 66 + kk + tg + 4];
        }
        uint32_t bfr[4][2];
        #pragma unroll
        for (int nt = 0; nt < 4; nt++) {
            int nn = wn * 32 + nt * 8 + gid;
            bfr[nt][0] = Ws[nn * 66 + kk + tg];
            bfr[nt][1] = Ws[nn * 66 + kk + tg + 4];
        }
        #pragma unroll
        for (int mt = 0; mt < 2; mt++)
            #pragma unroll
            for (int nt = 0; nt < 4; nt++)
                mma_tf32(acc[mt][nt], a[mt], bfr[nt]);
    }

    const int gate = blockIdx.y;  // PERM=0: 64-wide col tiles == one gate each

    #pragma unroll
    for (int mt = 0; mt < 2; mt++) {
        #pragma unroll
        for (int nt = 0; nt < 4; nt++) {
            int rloc = wm * 32 + mt * 16 + gid;
            int cc   = wn * 32 + nt * 8 + 2 * tg;
            float bv0 = Bs[cc], bv1 = Bs[cc + 1];
            #pragma unroll
            for (int half = 0; half < 2; half++) {
                int n = row0 + rloc + half * 8;
                float o0 = acc[mt][nt][half * 2] + bv0;
                float o1 = acc[mt][nt][half * 2 + 1] + bv1;
                if (PERM == 0) {
                    // interleaved: unit=cc, gate=blockIdx.y
                    float* base = out + (size_t)n * GG;
                    base[cc * 4 + gate]       = o0;
                    base[(cc + 1) * 4 + gate] = o1;
                } else {
                    int b = n & (BB - 1);
                    int t = n >> 9;
                    *(float2*)(out + ((size_t)b * TT + t) * DD + cc) =
                        make_float2(o0, o1);
                }
            }
        }
    }
}

// ---------------------------------------------------------------------------
// NARROW scan (R6 shape): 128 thr = 2 batches, grid 256, 2 blocks/SM.
// Best for store-bearing SMODE0 (co-resident block covers store/LDG latency).
// Thread: j = tid>>1 (unit), half = tid&1 (k-half; finish batch).
// xg is gate-interleaved: one float4 per (batch, unit) per step.
// ---------------------------------------------------------------------------
template<int XGC, int SMODE>
__global__ __launch_bounds__(128, 2) void lstm_scan_n(
    const float* __restrict__ xg,
    const float* __restrict__ Whh,
    float* __restrict__ hout)
{
    __shared__ float h_sh[2][2][2][36];  // [buf][batch][k-half-bucket][32+4]

    const int tid  = threadIdx.x;
    const int j    = tid >> 1;
    const int half = tid & 1;
    const int b0   = blockIdx.x * 2;
    const int bfin = b0 + half;

    u64 w2[4][16];
    #pragma unroll
    for (int g = 0; g < 4; g++) {
        const ulonglong2* wp =
            (const ulonglong2*)(Whh + (size_t)(g * 64 + j) * 64 + 32 * half);
        #pragma unroll
        for (int i = 0; i < 8; i++) {
            ulonglong2 v = wp[i];
            w2[g][2 * i] = v.x; w2[g][2 * i + 1] = v.y;
        }
    }

    for (int idx = tid; idx < 2 * 2 * 36; idx += 128)
        ((float*)h_sh[0])[idx] = 0.f;

    float4 xge = *(const float4*)(xg + (size_t)bfin * GG + j * 4);
    float c = 0.f;
    __syncthreads();

    for (int t = 0; t < TT; t++) {
        float4 cur = xge;
        if (!XGC && t + 1 < TT)
            xge = *(const float4*)(xg + ((size_t)(t + 1) * BB + bfin) * GG + j * 4);

        u64 hA[16], hB[16];
        {
            const ulonglong2* pA = (const ulonglong2*)&h_sh[t & 1][0][half][0];
            const ulonglong2* pB = (const ulonglong2*)&h_sh[t & 1][1][half][0];
            #pragma unroll
            for (int i = 0; i < 8; i++) {
                ulonglong2 vA = pA[i];
                ulonglong2 vB = pB[i];
                hA[2*i] = vA.x; hA[2*i+1] = vA.y;
                hB[2*i] = vB.x; hB[2*i+1] = vB.y;
            }
        }

        u64 accA[4] = {0ull, 0ull, 0ull, 0ull};
        u64 accB[4] = {0ull, 0ull, 0ull, 0ull};
        #pragma unroll
        for (int i = 0; i < 16; i++) {
            #pragma unroll
            for (int g = 0; g < 4; g++) {
                accA[g] = ffma2(hA[i], w2[g][i], accA[g]);
                accB[g] = ffma2(hB[i], w2[g][i], accB[g]);
            }
        }

        float curg[4] = {cur.x, cur.y, cur.z, cur.w};
        float tot[4];
        #pragma unroll
        for (int g = 0; g < 4; g++) {
            float2 pA2 = up2(accA[g]);
            float2 pB2 = up2(accB[g]);
            float sA = pA2.x + pA2.y;
            float sB = pB2.x + pB2.y;
            float mine = half ? sB : sA;
            float send = half ? sA : sB;
            tot[g] = mine + __shfl_xor_sync(0xFFFFFFFFu, send, 1) + curg[g];
        }

        float gi = fsigm(tot[0]);
        float gf = fsigm(tot[1]);
        float gc = ftanh(tot[2]);
        float go = fsigm(tot[3]);
        c = fmaf(gf, c, gi * gc);
        float h = go * ftanh(c);

        h_sh[(t + 1) & 1][half][j >> 5][j & 31] = h;
        if (SMODE == 0)
            hout[((size_t)t * BB + bfin) * HH + j] = h;
        if (SMODE == 1 && t == TT - 1)
            hout[(size_t)bfin * HH + j] = h;
        __syncthreads();
    }
}

// ---------------------------------------------------------------------------
// WIDE scan (R3 shape): 256 thr = 4 batches, grid 128 -> 1 block/SM uniform.
// Best measured shape for store-light scans (SMODE1): no co-tenant jitter.
// Thread: bp = tid>>7 (batch pair), par = tid&1 (k-half; batch parity),
// j = (tid>>1)&63. One shfl_xor(1) per gate with batch swap; one barrier.
// ---------------------------------------------------------------------------
template<int XGC, int SMODE>
__global__ __launch_bounds__(256, 1) void lstm_scan_w(
    const float* __restrict__ xg,
    const float* __restrict__ Whh,
    float* __restrict__ hout)
{
    __shared__ float h_sh[2][4][2][40];  // [buf][batch][k-half][32+8]

    const int tid = threadIdx.x;
    const int bp  = tid >> 7;
    const int par = tid & 1;
    const int j   = (tid >> 1) & 63;
    const int bA  = 2 * bp;
    const int b0  = blockIdx.x * 4;
    const int bfin = b0 + bA + par;

    u64 w2[4][16];
    #pragma unroll
    for (int g = 0; g < 4; g++) {
        const ulonglong2* wp =
            (const ulonglong2*)(Whh + (size_t)(g * 64 + j) * 64 + 32 * par);
        #pragma unroll
        for (int i = 0; i < 8; i++) {
            ulonglong2 v = wp[i];
            w2[g][2 * i] = v.x; w2[g][2 * i + 1] = v.y;
        }
    }

    for (int idx = tid; idx < 4 * 2 * 40; idx += 256)
        ((float*)h_sh[0])[idx] = 0.f;

    float4 xge = *(const float4*)(xg + (size_t)bfin * GG + j * 4);
    float c = 0.f;
    __syncthreads();

    for (int t = 0; t < TT; t++) {
        float4 cur = xge;
        if (!XGC && t + 1 < TT)
            xge = *(const float4*)(xg + ((size_t)(t + 1) * BB + bfin) * GG + j * 4);

        u64 acc0[4] = {0ull, 0ull, 0ull, 0ull};
        u64 acc1[4] = {0ull, 0ull, 0ull, 0ull};
        const ulonglong2* hb0 = (const ulonglong2*)&h_sh[t & 1][bA][par][0];
        const ulonglong2* hb1 = (const ulonglong2*)&h_sh[t & 1][bA + 1][par][0];
        #pragma unroll
        for (int i = 0; i < 8; i++) {
            ulonglong2 q0 = hb0[i];
            ulonglong2 q1 = hb1[i];
            #pragma unroll
            for (int g = 0; g < 4; g++) {
                acc0[g] = ffma2(q0.x, w2[g][2 * i],     acc0[g]);
                acc0[g] = ffma2(q0.y, w2[g][2 * i + 1], acc0[g]);
                acc1[g] = ffma2(q1.x, w2[g][2 * i],     acc1[g]);
                acc1[g] = ffma2(q1.y, w2[g][2 * i + 1], acc1[g]);
            }
        }

        float curg[4] = {cur.x, cur.y, cur.z, cur.w};
        float tot[4];
        #pragma unroll
        for (int g = 0; g < 4; g++) {
            float2 p0 = up2(acc0[g]);
            float2 p1 = up2(acc1[g]);
            float s0 = p0.x + p0.y;       // partial: batch bA,   my k-half
            float s1 = p1.x + p1.y;       // partial: batch bA+1, my k-half
            float send = par ? s0 : s1;
            float mine = par ? s1 : s0;
            float other = __shfl_xor_sync(0xFFFFFFFFu, send, 1);
            tot[g] = (mine + other) + curg[g];
        }

        float gi = fsigm(tot[0]);
        float gf = fsigm(tot[1]);
        float gc = ftanh(tot[2]);
        float go = fsigm(tot[3]);
        c = fmaf(gf, c, gi * gc);
        float h = go * ftanh(c);

        h_sh[(t + 1) & 1][bA + par][j >> 5][j & 31] = h;
        if (SMODE == 0)
            hout[((size_t)t * BB + bfin) * HH + j] = h;
        if (SMODE == 1 && t == TT - 1)
            hout[(size_t)bfin * HH + j] = h;
        __syncthreads();
    }
}

// ---------------------------------------------------------------------------
extern "C" void kernel_launch(void* const* d_in, const int* in_sizes, int n_in,
                              void* d_out, int out_size)
{
    (void)in_sizes; (void)n_in; (void)out_size;
    const float* x     = (const float*)d_in[0];
    const float* eWih0 = (const float*)d_in[1];
    const float* eWhh0 = (const float*)d_in[2];
    const float* ebih0 = (const float*)d_in[3];
    const float* ebhh0 = (const float*)d_in[4];
    const float* eWih1 = (const float*)d_in[5];
    const float* eWhh1 = (const float*)d_in[6];
    const float* ebih1 = (const float*)d_in[7];
    const float* ebhh1 = (const float*)d_in[8];
    const float* dWih0 = (const float*)d_in[9];
    const float* dWhh0 = (const float*)d_in[10];
    const float* dbih0 = (const float*)d_in[11];
    const float* dbhh0 = (const float*)d_in[12];
    const float* dWih1 = (const float*)d_in[13];
    const float* dWhh1 = (const float*)d_in[14];
    const float* dbih1 = (const float*)d_in[15];
    const float* dbhh1 = (const float*)d_in[16];
    const float* fcW   = (const float*)d_in[17];
    const float* fcb   = (const float*)d_in[18];
    float* out = (float*)d_out;

    float *xgp, *hseqp, *latp, *xgcp;
    cudaGetSymbolAddress((void**)&xgp,   g_xg);
    cudaGetSymbolAddress((void**)&hseqp, g_hseq);
    cudaGetSymbolAddress((void**)&latp,  g_lat);
    cudaGetSymbolAddress((void**)&xgcp,  g_xgc);

    const int smem_tc = (128 * 66 + 64 * 66) * 4 + 64 * 4;  // ~51 KB
    cudaFuncSetAttribute(gemm_tc<0>,
        cudaFuncAttributeMaxDynamicSharedMemorySize, smem_tc);
    cudaFuncSetAttribute(gemm_tc<1>,
        cudaFuncAttributeMaxDynamicSharedMemorySize, smem_tc);

    dim3 gbig(TT * BB / 128, GG / 64);  // (1024, 4)
    dim3 gsm(BB / 128, GG / 64);        // (4, 4)
    dim3 gscan_n(BB / 2);               // 256 narrow blocks (128 thr)
    dim3 gscan_w(BB / 4);               // 128 wide blocks (256 thr), 1/SM
    dim3 gfc(TT * BB / 128, 1);

    // Encoder layer 0 (store-heavy scan -> narrow)
    gemm_tc<0><<<gbig, 256, smem_tc>>>(x, TT * 64, 64, eWih0, ebih0, ebhh0, xgp, GG);
    lstm_scan_n<0, 0><<<gscan_n, 128>>>(xgp, eWhh0, hseqp);

    // Encoder layer 1 -> latent (store-light scan -> wide, 1 block/SM)
    gemm_tc<0><<<gbig, 256, smem_tc>>>(hseqp, 64, BB * 64, eWih1, ebih1, ebhh1, xgp, GG);
    lstm_scan_w<0, 1><<<gscan_w, 256>>>(xgp, eWhh1, latp);

    // Decoder layer 0 (constant xg; store-heavy -> narrow)
    gemm_tc<0><<<gsm, 256, smem_tc>>>(latp, 64, 0, dWih0, dbih0, dbhh0, xgcp, GG);
    lstm_scan_n<1, 0><<<gscan_n, 128>>>(xgcp, dWhh0, hseqp);

    // Decoder layer 1 (store-heavy -> narrow)
    gemm_tc<0><<<gbig, 256, smem_tc>>>(hseqp, 64, BB * 64, dWih1, dbih1, dbhh1, xgp, GG);
    lstm_scan_n<0, 0><<<gscan_n, 128>>>(xgp, dWhh1, hseqp);

    // Output projection (reads linear hseq; permuted store to [B][T][D])
    gemm_tc<1><<<gfc, 256, smem_tc>>>(hseqp, 64, BB * 64, fcW, fcb, nullptr, out, DD);
}

// round 11
// speedup vs baseline: 1.0122x; 1.0122x over previous
#include <cuda_runtime.h>
#include <cstdint>

#define BB 512   // batch
#define TT 256   // seq len
#define HH 64    // hidden
#define GG 256   // 4*H gates
#define DD 64    // input/output dim

// Scratch (static __device__ arrays — allocation-free per harness rules)
__device__ float g_xg[(size_t)TT * BB * GG];   // gate pre-acts [n][unit*4+gate]
__device__ float g_hseq[(size_t)TT * BB * HH]; // hidden sequence [T][B][H]
__device__ float g_lat[BB * HH];               // encoder latent [B][H]
__device__ float g_xgc[BB * GG];               // dec0 constant xg [B][unit*4+gate]

typedef unsigned long long u64;

__device__ __forceinline__ u64 ffma2(u64 a, u64 b, u64 c) {
    u64 d;
    asm("fma.rn.f32x2 %0, %1, %2, %3;" : "=l"(d) : "l"(a), "l"(b), "l"(c));
    return d;
}
__device__ __forceinline__ float2 up2(u64 v) {
    float lo, hi;
    asm("mov.b64 {%0, %1}, %2;" : "=f"(lo), "=f"(hi) : "l"(v));
    return make_float2(lo, hi);
}

__device__ __forceinline__ float fsigm(float x) {
    return __fdividef(1.0f, 1.0f + __expf(-x));
}
__device__ __forceinline__ float ftanh(float x) {
    return 1.0f - __fdividef(2.0f, __expf(2.0f * x) + 1.0f);
}

__device__ __forceinline__ uint32_t tf32_of(float x) {
    uint32_t u;
    asm("cvt.rna.tf32.f32 %0, %1;" : "=r"(u) : "f"(x));
    return u;
}

__device__ __forceinline__ void mma_tf32(
    float* d, const uint32_t* a, const uint32_t* b)
{
    asm volatile(
        "mma.sync.aligned.m16n8k8.row.col.f32.tf32.tf32.f32 "
        "{%0,%1,%2,%3}, {%4,%5,%6,%7}, {%8,%9}, {%0,%1,%2,%3};"
        : "+f"(d[0]), "+f"(d[1]), "+f"(d[2]), "+f"(d[3])
        : "r"(a[0]), "r"(a[1]), "r"(a[2]), "r"(a[3]),
          "r"(b[0]), "r"(b[1]));
}

// ---------------------------------------------------------------------------
// Tensor-core tf32 GEMM: sum_k X[row n][k] * W[col][k] + bias.
// X row n addressed via n = t*BB + b -> X + b*st_b + t*st_t (+k). K = 64.
// Block tile 128(m) x 64(n), 256 threads = 8 warps (4m x 2n), warp tile 32x32.
// PERM=0 (xg): blockIdx.y IS the gate (64-col tiles align with gates);
//   store interleaved: out[n*GG + unit*4 + gate], unit = cc.
// PERM=1 (FC): out[(b*TT+t)*DD + cc] float2.
// ---------------------------------------------------------------------------
template<int PERM>
__global__ __launch_bounds__(256) void gemm_tc(
    const float* __restrict__ X, int st_b, int st_t,
    const float* __restrict__ W,
    const float* __restrict__ bias1, const float* __restrict__ bias2,
    float* __restrict__ out, int ostride)
{
    extern __shared__ uint32_t smu[];
    uint32_t* Xs = smu;                    // [128][66]
    uint32_t* Ws = smu + 128 * 66;         // [64][66]
    float*    Bs = (float*)(smu + 128 * 66 + 64 * 66);  // [64]

    const int tid  = threadIdx.x;
    const int row0 = blockIdx.x * 128;
    const int col0 = blockIdx.y * 64;

    #pragma unroll
    for (int i = 0; i < 8; i++) {
        int idx = tid + i * 256;
        int m   = idx & 127;
        int k4  = idx >> 7;
        int n   = row0 + m;
        int b   = n & (BB - 1);
        int t   = n >> 9;
        float4 v = *(const float4*)(X + (size_t)b * st_b + (size_t)t * st_t + k4 * 4);
        uint32_t* p = Xs + m * 66 + k4 * 4;
        p[0] = tf32_of(v.x); p[1] = tf32_of(v.y);
        p[2] = tf32_of(v.z); p[3] = tf32_of(v.w);
    }
    #pragma unroll
    for (int i = 0; i < 4; i++) {
        int idx = tid + i * 256;
        int g   = idx & 63;
        int k4  = idx >> 6;
        float4 v = *(const float4*)(W + (size_t)(col0 + g) * 64 + k4 * 4);
        uint32_t* p = Ws + g * 66 + k4 * 4;
        p[0] = tf32_of(v.x); p[1] = tf32_of(v.y);
        p[2] = tf32_of(v.z); p[3] = tf32_of(v.w);
    }
    if (tid < 64)
        Bs[tid] = (bias1 ? bias1[col0 + tid] : 0.f)
                + (bias2 ? bias2[col0 + tid] : 0.f);
    __syncthreads();

    const int lane = tid & 31;
    const int gid  = lane >> 2;
    const int tg   = lane & 3;
    const int warp = tid >> 5;
    const int wm   = warp & 3;
    const int wn   = warp >> 2;

    float acc[2][4][4];
    #pragma unroll
    for (int mt = 0; mt < 2; mt++)
        #pragma unroll
        for (int nt = 0; nt < 4; nt++)
            #pragma unroll
            for (int r = 0; r < 4; r++) acc[mt][nt][r] = 0.f;

    #pragma unroll
    for (int s = 0; s < 8; s++) {
        const int kk = s * 8;
        uint32_t a[2][4];
        #pragma unroll
        for (int mt = 0; mt < 2; mt++) {
            int r = wm * 32 + mt * 16 + gid;
            a[mt][0] = Xs[r * 66 + kk + tg];
            a[mt][1] = Xs[(r + 8) * 66 + kk + tg];
            a[mt][2] = Xs[r * 66 + kk + tg + 4];
            a[mt][3] = Xs[(r + 8) * 66 + kk + tg + 4];
        }
        uint32_t bfr[4][2];
        #pragma unroll
        for (int nt = 0; nt < 4; nt++) {
            int nn = wn * 32 + nt * 8 + gid;
            bfr[nt][0] = Ws[nn * 66 + kk + tg];
            bfr[nt][1] = Ws[nn * 66 + kk + tg + 4];
        }
        #pragma unroll
        for (int mt = 0; mt < 2; mt++)
            #pragma unroll
            for (int nt = 0; nt < 4; nt++)
                mma_tf32(acc[mt][nt], a[mt], bfr[nt]);
    }

    const int gate = blockIdx.y;  // PERM=0: 64-wide col tiles == one gate each

    #pragma unroll
    for (int mt = 0; mt < 2; mt++) {
        #pragma unroll
        for (int nt = 0; nt < 4; nt++) {
            int rloc = wm * 32 + mt * 16 + gid;
            int cc   = wn * 32 + nt * 8 + 2 * tg;
            float bv0 = Bs[cc], bv1 = Bs[cc + 1];
            #pragma unroll
            for (int half = 0; half < 2; half++) {
                int n = row0 + rloc + half * 8;
                float o0 = acc[mt][nt][half * 2] + bv0;
                float o1 = acc[mt][nt][half * 2 + 1] + bv1;
                if (PERM == 0) {
                    // interleaved: unit=cc, gate=blockIdx.y
                    float* base = out + (size_t)n * GG;
                    base[cc * 4 + gate]       = o0;
                    base[(cc + 1) * 4 + gate] = o1;
                } else {
                    int b = n & (BB - 1);
                    int t = n >> 9;
                    *(float2*)(out + ((size_t)b * TT + t) * DD + cc) =
                        make_float2(o0, o1);
                }
            }
        }
    }
}

// ---------------------------------------------------------------------------
// NARROW scan (R6 shape): 128 thr = 2 batches, grid 256, 2 blocks/SM.
// Best for store-bearing SMODE0 (co-resident block covers store/LDG latency).
// Thread: j = tid>>1 (unit), half = tid&1 (k-half; finish batch).
// xg is gate-interleaved: one float4 per (batch, unit) per step.
// ---------------------------------------------------------------------------
template<int XGC, int SMODE>
__global__ __launch_bounds__(128, 2) void lstm_scan_n(
    const float* __restrict__ xg,
    const float* __restrict__ Whh,
    float* __restrict__ hout)
{
    __shared__ float h_sh[2][2][2][36];  // [buf][batch][k-half-bucket][32+4]

    const int tid  = threadIdx.x;
    const int j    = tid >> 1;
    const int half = tid & 1;
    const int b0   = blockIdx.x * 2;
    const int bfin = b0 + half;

    u64 w2[4][16];
    #pragma unroll
    for (int g = 0; g < 4; g++) {
        const ulonglong2* wp =
            (const ulonglong2*)(Whh + (size_t)(g * 64 + j) * 64 + 32 * half);
        #pragma unroll
        for (int i = 0; i < 8; i++) {
            ulonglong2 v = wp[i];
            w2[g][2 * i] = v.x; w2[g][2 * i + 1] = v.y;
        }
    }

    for (int idx = tid; idx < 2 * 2 * 36; idx += 128)
        ((float*)h_sh[0])[idx] = 0.f;

    float4 xge = *(const float4*)(xg + (size_t)bfin * GG + j * 4);
    float c = 0.f;
    __syncthreads();

    for (int t = 0; t < TT; t++) {
        float4 cur = xge;
        if (!XGC && t + 1 < TT)
            xge = *(const float4*)(xg + ((size_t)(t + 1) * BB + bfin) * GG + j * 4);

        u64 hA[16], hB[16];
        {
            const ulonglong2* pA = (const ulonglong2*)&h_sh[t & 1][0][half][0];
            const ulonglong2* pB = (const ulonglong2*)&h_sh[t & 1][1][half][0];
            #pragma unroll
            for (int i = 0; i < 8; i++) {
                ulonglong2 vA = pA[i];
                ulonglong2 vB = pB[i];
                hA[2*i] = vA.x; hA[2*i+1] = vA.y;
                hB[2*i] = vB.x; hB[2*i+1] = vB.y;
            }
        }

        u64 accA[4] = {0ull, 0ull, 0ull, 0ull};
        u64 accB[4] = {0ull, 0ull, 0ull, 0ull};
        #pragma unroll
        for (int i = 0; i < 16; i++) {
            #pragma unroll
            for (int g = 0; g < 4; g++) {
                accA[g] = ffma2(hA[i], w2[g][i], accA[g]);
                accB[g] = ffma2(hB[i], w2[g][i], accB[g]);
            }
        }

        float curg[4] = {cur.x, cur.y, cur.z, cur.w};
        float tot[4];
        #pragma unroll
        for (int g = 0; g < 4; g++) {
            float2 pA2 = up2(accA[g]);
            float2 pB2 = up2(accB[g]);
            float sA = pA2.x + pA2.y;
            float sB = pB2.x + pB2.y;
            float mine = half ? sB : sA;
            float send = half ? sA : sB;
            tot[g] = mine + __shfl_xor_sync(0xFFFFFFFFu, send, 1) + curg[g];
        }

        float gi = fsigm(tot[0]);
        float gf = fsigm(tot[1]);
        float gc = ftanh(tot[2]);
        float go = fsigm(tot[3]);
        c = fmaf(gf, c, gi * gc);
        float h = go * ftanh(c);

        h_sh[(t + 1) & 1][half][j >> 5][j & 31] = h;
        if (SMODE == 0)
            hout[((size_t)t * BB + bfin) * HH + j] = h;
        if (SMODE == 1 && t == TT - 1)
            hout[(size_t)bfin * HH + j] = h;
        __syncthreads();
    }
}

// ---------------------------------------------------------------------------
// WIDE scan (R3 shape): 256 thr = 4 batches, grid 128 -> 1 block/SM uniform.
// Best measured shape for store-light scans (SMODE1): no co-tenant jitter.
// Thread: bp = tid>>7 (batch pair), par = tid&1 (k-half; batch parity),
// j = (tid>>1)&63. One shfl_xor(1) per gate with batch swap; one barrier.
// ---------------------------------------------------------------------------
template<int XGC, int SMODE>
__global__ __launch_bounds__(256, 1) void lstm_scan_w(
    const float* __restrict__ xg,
    const float* __restrict__ Whh,
    float* __restrict__ hout)
{
    __shared__ float h_sh[2][4][2][40];  // [buf][batch][k-half][32+8]

    const int tid = threadIdx.x;
    const int bp  = tid >> 7;
    const int par = tid & 1;
    const int j   = (tid >> 1) & 63;
    const int bA  = 2 * bp;
    const int b0  = blockIdx.x * 4;
    const int bfin = b0 + bA + par;

    u64 w2[4][16];
    #pragma unroll
    for (int g = 0; g < 4; g++) {
        const ulonglong2* wp =
            (const ulonglong2*)(Whh + (size_t)(g * 64 + j) * 64 + 32 * par);
        #pragma unroll
        for (int i = 0; i < 8; i++) {
            ulonglong2 v = wp[i];
            w2[g][2 * i] = v.x; w2[g][2 * i + 1] = v.y;
        }
    }

    for (int idx = tid; idx < 4 * 2 * 40; idx += 256)
        ((float*)h_sh[0])[idx] = 0.f;

    float4 xge = *(const float4*)(xg + (size_t)bfin * GG + j * 4);
    float c = 0.f;
    __syncthreads();

    for (int t = 0; t < TT; t++) {
        float4 cur = xge;
        if (!XGC && t + 1 < TT)
            xge = *(const float4*)(xg + ((size_t)(t + 1) * BB + bfin) * GG + j * 4);

        u64 acc0[4] = {0ull, 0ull, 0ull, 0ull};
        u64 acc1[4] = {0ull, 0ull, 0ull, 0ull};
        const ulonglong2* hb0 = (const ulonglong2*)&h_sh[t & 1][bA][par][0];
        const ulonglong2* hb1 = (const ulonglong2*)&h_sh[t & 1][bA + 1][par][0];
        #pragma unroll
        for (int i = 0; i < 8; i++) {
            ulonglong2 q0 = hb0[i];
            ulonglong2 q1 = hb1[i];
            #pragma unroll
            for (int g = 0; g < 4; g++) {
                acc0[g] = ffma2(q0.x, w2[g][2 * i],     acc0[g]);
                acc0[g] = ffma2(q0.y, w2[g][2 * i + 1], acc0[g]);
                acc1[g] = ffma2(q1.x, w2[g][2 * i],     acc1[g]);
                acc1[g] = ffma2(q1.y, w2[g][2 * i + 1], acc1[g]);
            }
        }

        float curg[4] = {cur.x, cur.y, cur.z, cur.w};
        float tot[4];
        #pragma unroll
        for (int g = 0; g < 4; g++) {
            float2 p0 = up2(acc0[g]);
            float2 p1 = up2(acc1[g]);
            float s0 = p0.x + p0.y;       // partial: batch bA,   my k-half
            float s1 = p1.x + p1.y;       // partial: batch bA+1, my k-half
            float send = par ? s0 : s1;
            float mine = par ? s1 : s0;
            float other = __shfl_xor_sync(0xFFFFFFFFu, send, 1);
            tot[g] = (mine + other) + curg[g];
        }

        float gi = fsigm(tot[0]);
        float gf = fsigm(tot[1]);
        float gc = ftanh(tot[2]);
        float go = fsigm(tot[3]);
        c = fmaf(gf, c, gi * gc);
        float h = go * ftanh(c);

        h_sh[(t + 1) & 1][bA + par][j >> 5][j & 31] = h;
        if (SMODE == 0)
            hout[((size_t)t * BB + bfin) * HH + j] = h;
        if (SMODE == 1 && t == TT - 1)
            hout[(size_t)bfin * HH + j] = h;
        __syncthreads();
    }
}

// ---------------------------------------------------------------------------
extern "C" void kernel_launch(void* const* d_in, const int* in_sizes, int n_in,
                              void* d_out, int out_size)
{
    (void)in_sizes; (void)n_in; (void)out_size;
    const float* x     = (const float*)d_in[0];
    const float* eWih0 = (const float*)d_in[1];
    const float* eWhh0 = (const float*)d_in[2];
    const float* ebih0 = (const float*)d_in[3];
    const float* ebhh0 = (const float*)d_in[4];
    const float* eWih1 = (const float*)d_in[5];
    const float* eWhh1 = (const float*)d_in[6];
    const float* ebih1 = (const float*)d_in[7];
    const float* ebhh1 = (const float*)d_in[8];
    const float* dWih0 = (const float*)d_in[9];
    const float* dWhh0 = (const float*)d_in[10];
    const float* dbih0 = (const float*)d_in[11];
    const float* dbhh0 = (const float*)d_in[12];
    const float* dWih1 = (const float*)d_in[13];
    const float* dWhh1 = (const float*)d_in[14];
    const float* dbih1 = (const float*)d_in[15];
    const float* dbhh1 = (const float*)d_in[16];
    const float* fcW   = (const float*)d_in[17];
    const float* fcb   = (const float*)d_in[18];
    float* out = (float*)d_out;

    float *xgp, *hseqp, *latp, *xgcp;
    cudaGetSymbolAddress((void**)&xgp,   g_xg);
    cudaGetSymbolAddress((void**)&hseqp, g_hseq);
    cudaGetSymbolAddress((void**)&latp,  g_lat);
    cudaGetSymbolAddress((void**)&xgcp,  g_xgc);

    const int smem_tc = (128 * 66 + 64 * 66) * 4 + 64 * 4;  // ~51 KB
    cudaFuncSetAttribute(gemm_tc<0>,
        cudaFuncAttributeMaxDynamicSharedMemorySize, smem_tc);
    cudaFuncSetAttribute(gemm_tc<1>,
        cudaFuncAttributeMaxDynamicSharedMemorySize, smem_tc);

    dim3 gbig(TT * BB / 128, GG / 64);  // (1024, 4)
    dim3 gsm(BB / 128, GG / 64);        // (4, 4)
    dim3 gscan_n(BB / 2);               // 256 narrow blocks (128 thr)
    dim3 gscan_w(BB / 4);               // 128 wide blocks (256 thr), 1/SM
    dim3 gfc(TT * BB / 128, 1);

    // Encoder layer 0 (store-heavy scan -> narrow)
    gemm_tc<0><<<gbig, 256, smem_tc>>>(x, TT * 64, 64, eWih0, ebih0, ebhh0, xgp, GG);
    lstm_scan_n<0, 0><<<gscan_n, 128>>>(xgp, eWhh0, hseqp);

    // Encoder layer 1 -> latent (store-light scan -> wide, 1 block/SM)
    gemm_tc<0><<<gbig, 256, smem_tc>>>(hseqp, 64, BB * 64, eWih1, ebih1, ebhh1, xgp, GG);
    lstm_scan_w<0, 1><<<gscan_w, 256>>>(xgp, eWhh1, latp);

    // Decoder layer 0 (constant xg; store-heavy -> narrow)
    gemm_tc<0><<<gsm, 256, smem_tc>>>(latp, 64, 0, dWih0, dbih0, dbhh0, xgcp, GG);
    lstm_scan_n<1, 0><<<gscan_n, 128>>>(xgcp, dWhh0, hseqp);

    // Decoder layer 1 (store-heavy -> narrow)
    gemm_tc<0><<<gbig, 256, smem_tc>>>(hseqp, 64, BB * 64, dWih1, dbih1, dbhh1, xgp, GG);
    lstm_scan_n<0, 0><<<gscan_n, 128>>>(xgp, dWhh1, hseqp);

    // Output projection (reads linear hseq; permuted store to [B][T][D])
    gemm_tc<1><<<gfc, 256, smem_tc>>>(hseqp, 64, BB * 64, fcW, fcb, nullptr, out, DD);
}